// round 2
// baseline (speedup 1.0000x reference)
#include <cuda_runtime.h>
#include <cuda_fp16.h>
#include <math.h>

#define N_NODES 50000
#define E_MAX   800000
#define SCAN_BLOCKS 196   // 196*256 = 50176 >= 50000

// ---------------- static device scratch ----------------
__device__ float  g_tfeat[(size_t)E_MAX * 32];  // sorted edge order, 102.4 MB
__device__ float  g_q  [N_NODES * 128];
__device__ __half g_kh [N_NODES * 128];
__device__ __half g_vh [N_NODES * 128];
__device__ float  g_qt [N_NODES * 128];
__device__ float  g_qbt[N_NODES * 4];
__device__ float  g_x1 [N_NODES * 128];
__device__ float  g_x2 [N_NODES * 128];
__device__ float  g_xc [N_NODES];
__device__ int    g_deg[N_NODES];
__device__ int    g_cur[N_NODES];
__device__ int    g_off[N_NODES + 1];
__device__ int    g_bsum[SCAN_BLOCKS];
__device__ int    g_bpre[SCAN_BLOCKS];
__device__ int    g_ssrc[E_MAX];   // src node, sorted by dst
__device__ float  g_et  [E_MAX];   // time value, sorted by dst

// ---------------- counting sort of edges by dst ----------------
__global__ void zero_kernel() {
    int i = blockIdx.x * blockDim.x + threadIdx.x;
    if (i < N_NODES) { g_deg[i] = 0; g_cur[i] = 0; }
}

__global__ void hist_kernel(const int* __restrict__ ei, int E) {
    int e = blockIdx.x * blockDim.x + threadIdx.x;
    if (e < E) atomicAdd(&g_deg[ei[E + e]], 1);
}

// block-level exclusive scan; emit block totals
__global__ void scanA_kernel(int n) {
    __shared__ int sh[256];
    int t = threadIdx.x;
    int i = blockIdx.x * 256 + t;
    int v = (i < n) ? g_deg[i] : 0;
    sh[t] = v;
    __syncthreads();
    for (int o = 1; o < 256; o <<= 1) {
        int u = (t >= o) ? sh[t - o] : 0;
        __syncthreads();
        sh[t] += u;
        __syncthreads();
    }
    if (i < n) g_off[i] = sh[t] - v;            // exclusive within block
    if (t == 255) g_bsum[blockIdx.x] = sh[255]; // block total
}

// scan the block totals (single block)
__global__ void scanB_kernel(int nb, int n) {
    __shared__ int sh[256];
    int t = threadIdx.x;
    int v = (t < nb) ? g_bsum[t] : 0;
    sh[t] = v;
    __syncthreads();
    for (int o = 1; o < 256; o <<= 1) {
        int u = (t >= o) ? sh[t - o] : 0;
        __syncthreads();
        sh[t] += u;
        __syncthreads();
    }
    if (t < nb) g_bpre[t] = sh[t] - v;
    if (t == 255) g_off[n] = sh[255];           // grand total = E
}

__global__ void scanC_kernel(int n) {
    int i = blockIdx.x * 256 + threadIdx.x;
    if (i < n) g_off[i] += g_bpre[blockIdx.x];
}

// scatter edges to dst-sorted positions, materializing (src, t) directly
__global__ void scatter_kernel(const int* __restrict__ ei,
                               const float* __restrict__ ea, int E) {
    int e = blockIdx.x * blockDim.x + threadIdx.x;
    if (e >= E) return;
    int d = ei[E + e];
    int pos = g_off[d] + atomicAdd(&g_cur[d], 1);
    g_ssrc[pos] = ei[e];
    g_et[pos]   = ea[2 * e + 1];
}

// ---------------- time encoding in sorted order ----------------
__global__ void tfeat_kernel(int E) {
    int idx = blockIdx.x * blockDim.x + threadIdx.x;
    if (idx >= E) return;
    float t = g_et[idx];
    // div_term[i] = 10^(-i/4)
    const float dv[16] = {
        1.0f, 0.562341325f, 0.316227766f, 0.177827941f,
        0.1f, 0.0562341325f, 0.0316227766f, 0.0177827941f,
        0.01f, 0.00562341325f, 0.00316227766f, 0.00177827941f,
        0.001f, 0.000562341325f, 0.000316227766f, 0.000177827941f};
    float buf[32];
#pragma unroll
    for (int i = 0; i < 16; i++) {
        float a = t * dv[i];
        buf[2 * i]     = __sinf(a);
        buf[2 * i + 1] = __cosf(a);
    }
    float4* dst = reinterpret_cast<float4*>(g_tfeat + (size_t)idx * 32);
#pragma unroll
    for (int i = 0; i < 8; i++) dst[i] = reinterpret_cast<float4*>(buf)[i];
}

// ---------------- fused node linear: q, k(fp16), v(fp16), qt, qbt ----------------
template <int D>
__global__ __launch_bounds__(128) void node_linear_kernel(
    const float* __restrict__ x_in,
    const float* __restrict__ wq, const float* __restrict__ bq,
    const float* __restrict__ wk, const float* __restrict__ bk,
    const float* __restrict__ wv, const float* __restrict__ bv,
    const float* __restrict__ wt, const float* __restrict__ bt)
{
    const float* __restrict__ x = (D == 64) ? x_in : (const float*)g_x1;
    __shared__ float xs[D * 16];        // transposed: xs[c*16 + n]
    __shared__ float qs[16 * 128];
    __shared__ float wtt[128 * 33];     // wtt[ho*33 + d] = wt[d*128 + ho]
    int col = threadIdx.x;              // 0..127
    int node0 = blockIdx.x * 16;

    for (int idx = col; idx < 16 * D; idx += 128) {
        int n = idx / D, c = idx % D;
        int node = node0 + n;
        xs[c * 16 + n] = (node < N_NODES) ? x[(size_t)node * D + c] : 0.f;
    }
    for (int idx = col; idx < 32 * 128; idx += 128) {
        int d = idx >> 7, ho = idx & 127;
        wtt[ho * 33 + d] = wt[idx];
    }
    __syncthreads();

    float aq[16], ak[16], av[16];
#pragma unroll
    for (int n = 0; n < 16; n++) { aq[n] = 0.f; ak[n] = 0.f; av[n] = 0.f; }

    const float4* xs4 = reinterpret_cast<const float4*>(xs);
    for (int c = 0; c < D; c++) {
        float wqc = wq[c * 128 + col];
        float wkc = wk[c * 128 + col];
        float wvc = wv[c * 128 + col];
        float4 a = xs4[c * 4 + 0], b = xs4[c * 4 + 1];
        float4 cc = xs4[c * 4 + 2], dd = xs4[c * 4 + 3];
        float xv[16] = {a.x, a.y, a.z, a.w, b.x, b.y, b.z, b.w,
                        cc.x, cc.y, cc.z, cc.w, dd.x, dd.y, dd.z, dd.w};
#pragma unroll
        for (int n = 0; n < 16; n++) {
            aq[n] = fmaf(xv[n], wqc, aq[n]);
            ak[n] = fmaf(xv[n], wkc, ak[n]);
            av[n] = fmaf(xv[n], wvc, av[n]);
        }
    }

    float bqc = bq[col], bkc = bk[col], bvc = bv[col];
    const float inv = 0.17677669529663688f;  // 1/sqrt(32)
#pragma unroll
    for (int n = 0; n < 16; n++) {
        int node = node0 + n;
        float qv = (aq[n] + bqc) * inv;
        qs[n * 128 + col] = qv;
        if (node < N_NODES) {
            g_q [node * 128 + col] = qv;
            g_kh[node * 128 + col] = __float2half(ak[n] + bkc);
            g_vh[node * 128 + col] = __float2half(av[n] + bvc);
        }
    }
    __syncthreads();

    int h = col >> 5, d = col & 31;
    float aqt[16];
#pragma unroll
    for (int n = 0; n < 16; n++) aqt[n] = 0.f;
    for (int c = 0; c < 32; c++) {
        float w = wtt[(h * 32 + c) * 33 + d];
#pragma unroll
        for (int n = 0; n < 16; n++)
            aqt[n] = fmaf(qs[n * 128 + h * 32 + c], w, aqt[n]);
    }
#pragma unroll
    for (int n = 0; n < 16; n++) {
        int node = node0 + n;
        if (node < N_NODES) g_qt[node * 128 + col] = aqt[n];
    }

    if (col < 4) {
        for (int n = 0; n < 16; n++) {
            int node = node0 + n;
            if (node >= N_NODES) break;
            float b = 0.f;
            for (int c = 0; c < 32; c++)
                b = fmaf(qs[n * 128 + col * 32 + c], bt[col * 32 + c], b);
            g_qbt[node * 4 + col] = b;
        }
    }
}

// ---------------- per-node softmax aggregation (warp = node, 4 heads) ----------------
__device__ __forceinline__ float head_alpha(float4 q4, float4 qt4,
                                            float2 k01, float2 k23, float4 tf) {
    float p = q4.x * k01.x;
    p = fmaf(q4.y,  k01.y, p);
    p = fmaf(q4.z,  k23.x, p);
    p = fmaf(q4.w,  k23.y, p);
    p = fmaf(qt4.x, tf.x, p);
    p = fmaf(qt4.y, tf.y, p);
    p = fmaf(qt4.z, tf.z, p);
    p = fmaf(qt4.w, tf.w, p);
    p += __shfl_xor_sync(0xffffffffu, p, 4);
    p += __shfl_xor_sync(0xffffffffu, p, 2);
    p += __shfl_xor_sync(0xffffffffu, p, 1);
    return p;
}

__global__ __launch_bounds__(256) void edge_agg_kernel(int layer) {
    int lane = threadIdx.x & 31;
    int node = blockIdx.x * 8 + (threadIdx.x >> 5);
    if (node >= N_NODES) return;
    float* __restrict__ xout = (layer == 0) ? g_x1 : g_x2;

    int idx = g_off[node], end = g_off[node + 1];
    if (idx >= end) {
        reinterpret_cast<float4*>(xout + (size_t)node * 128)[lane] =
            make_float4(0.f, 0.f, 0.f, 0.f);
        return;
    }

    float4 q4  = reinterpret_cast<const float4*>(g_q  + (size_t)node * 128)[lane];
    float4 qt4 = reinterpret_cast<const float4*>(g_qt + (size_t)node * 128)[lane];
    float qbt  = g_qbt[node * 4 + (lane >> 3)];

    const float2* kh = reinterpret_cast<const float2*>(g_kh);  // 4 halves per float2
    const float2* vh = reinterpret_cast<const float2*>(g_vh);
    const float4* tfp = reinterpret_cast<const float4*>(g_tfeat);

    float s, ref;
    float4 acc;
    {   // peel first edge: reference point for exp
        int cs = g_ssrc[idx];
        float2 kraw = kh[(size_t)cs * 32 + lane];
        float2 vraw = vh[(size_t)cs * 32 + lane];
        float4 tf   = tfp[(size_t)idx * 8 + (lane & 7)];
        float2 k01 = __half22float2(*reinterpret_cast<__half2*>(&kraw.x));
        float2 k23 = __half22float2(*reinterpret_cast<__half2*>(&kraw.y));
        float2 v01 = __half22float2(*reinterpret_cast<__half2*>(&vraw.x));
        float2 v23 = __half22float2(*reinterpret_cast<__half2*>(&vraw.y));
        ref = head_alpha(q4, qt4, k01, k23, tf) + qbt;
        s = 1.f;
        acc = make_float4(v01.x, v01.y, v23.x, v23.y);
    }
    idx++;

#pragma unroll 4
    for (; idx < end; idx++) {
        int cs = g_ssrc[idx];
        float2 kraw = kh[(size_t)cs * 32 + lane];
        float2 vraw = vh[(size_t)cs * 32 + lane];
        float4 tf   = tfp[(size_t)idx * 8 + (lane & 7)];
        float2 k01 = __half22float2(*reinterpret_cast<__half2*>(&kraw.x));
        float2 k23 = __half22float2(*reinterpret_cast<__half2*>(&kraw.y));
        float2 v01 = __half22float2(*reinterpret_cast<__half2*>(&vraw.x));
        float2 v23 = __half22float2(*reinterpret_cast<__half2*>(&vraw.y));
        float alpha = head_alpha(q4, qt4, k01, k23, tf) + qbt;
        float pe = __expf(fminf(alpha - ref, 80.f));
        s += pe;
        acc.x = fmaf(pe, v01.x, acc.x);
        acc.y = fmaf(pe, v01.y, acc.y);
        acc.z = fmaf(pe, v23.x, acc.z);
        acc.w = fmaf(pe, v23.y, acc.w);
    }

    float r = 1.f / s;   // s >= 1 (first term is exp(0))
    float4 o = make_float4(fmaxf(acc.x * r, 0.f), fmaxf(acc.y * r, 0.f),
                           fmaxf(acc.z * r, 0.f), fmaxf(acc.w * r, 0.f));
    reinterpret_cast<float4*>(xout + (size_t)node * 128)[lane] = o;
}

// ---------------- final classifier ----------------
__global__ void xc_kernel(const float* __restrict__ wc) {
    int lane = threadIdx.x & 31;
    int node = blockIdx.x * 8 + (threadIdx.x >> 5);
    if (node >= N_NODES) return;
    const float* xr = g_x2 + (size_t)node * 128;
    float p = xr[lane] * wc[lane] + xr[lane + 32] * wc[lane + 32] +
              xr[lane + 64] * wc[lane + 64] + xr[lane + 96] * wc[lane + 96];
#pragma unroll
    for (int o = 16; o; o >>= 1) p += __shfl_xor_sync(0xffffffffu, p, o);
    if (lane == 0) g_xc[node] = p;
}

__global__ void final_kernel(const int* __restrict__ ei, const float* __restrict__ bc,
                             float* __restrict__ out, int E) {
    int e = blockIdx.x * blockDim.x + threadIdx.x;
    if (e >= E) return;
    out[e] = g_xc[ei[e]] + g_xc[ei[E + e]] + bc[0];
}

// ---------------- launch ----------------
extern "C" void kernel_launch(void* const* d_in, const int* in_sizes, int n_in,
                              void* d_out, int out_size) {
    const int*   ei  = (const int*)  d_in[0];
    const float* ea  = (const float*)d_in[1];
    const float* emb = (const float*)d_in[3];
    const float *wq1 = (const float*)d_in[4],  *bq1 = (const float*)d_in[5];
    const float *wk1 = (const float*)d_in[6],  *bk1 = (const float*)d_in[7];
    const float *wv1 = (const float*)d_in[8],  *bv1 = (const float*)d_in[9];
    const float *wt1 = (const float*)d_in[10], *bt1 = (const float*)d_in[11];
    const float *wq2 = (const float*)d_in[12], *bq2 = (const float*)d_in[13];
    const float *wk2 = (const float*)d_in[14], *bk2 = (const float*)d_in[15];
    const float *wv2 = (const float*)d_in[16], *bv2 = (const float*)d_in[17];
    const float *wt2 = (const float*)d_in[18], *bt2 = (const float*)d_in[19];
    const float *wc  = (const float*)d_in[20], *bc  = (const float*)d_in[21];
    float* out = (float*)d_out;

    int E = in_sizes[0] / 2;

    zero_kernel<<<(N_NODES + 255) / 256, 256>>>();
    hist_kernel<<<(E + 255) / 256, 256>>>(ei, E);
    scanA_kernel<<<SCAN_BLOCKS, 256>>>(N_NODES);
    scanB_kernel<<<1, 256>>>(SCAN_BLOCKS, N_NODES);
    scanC_kernel<<<SCAN_BLOCKS, 256>>>(N_NODES);
    scatter_kernel<<<(E + 255) / 256, 256>>>(ei, ea, E);
    tfeat_kernel<<<(E + 255) / 256, 256>>>(E);

    // layer 1 (x = emb[:N], D=64)
    node_linear_kernel<64><<<(N_NODES + 15) / 16, 128>>>(emb, wq1, bq1, wk1, bk1, wv1, bv1, wt1, bt1);
    edge_agg_kernel<<<(N_NODES + 7) / 8, 256>>>(0);

    // layer 2 (x = g_x1, D=128)
    node_linear_kernel<128><<<(N_NODES + 15) / 16, 128>>>(emb, wq2, bq2, wk2, bk2, wv2, bv2, wt2, bt2);
    edge_agg_kernel<<<(N_NODES + 7) / 8, 256>>>(1);

    xc_kernel<<<(N_NODES + 7) / 8, 256>>>(wc);
    final_kernel<<<(E + 255) / 256, 256>>>(ei, bc, out, E);
}

// round 4
// speedup vs baseline: 1.7303x; 1.7303x over previous
#include <cuda_runtime.h>
#include <cuda_fp16.h>
#include <math.h>

#define N_NODES 50000
#define E_MAX   800000
#define SCAN_BLOCKS 196   // 196*256 = 50176 >= 50000

// div_term[i] = 10^(-i/4) = exp(-i*ln(10000)/16), i = 0..15 (exact table)
__constant__ float c_dv[16] = {
    1.0f, 0.5623413251903491f, 0.31622776601683794f, 0.17782794100389228f,
    0.1f, 0.05623413251903491f, 0.031622776601683794f, 0.017782794100389228f,
    0.01f, 0.005623413251903491f, 0.0031622776601683794f, 0.0017782794100389228f,
    0.001f, 0.0005623413251903491f, 0.00031622776601683794f, 0.00017782794100389228f};

// ---------------- static device scratch ----------------
__device__ float  g_q  [N_NODES * 128];
__device__ __half g_kh [N_NODES * 128];
__device__ __half g_vh [N_NODES * 128];
__device__ float  g_qt [N_NODES * 128];
__device__ float  g_qbt[N_NODES * 4];
__device__ float  g_x1 [N_NODES * 128];
__device__ float  g_xc [N_NODES];
__device__ int    g_deg[N_NODES];
__device__ int    g_cur[N_NODES];
__device__ int    g_off[N_NODES + 1];
__device__ int    g_bsum[SCAN_BLOCKS];
__device__ int    g_bpre[SCAN_BLOCKS];
__device__ int    g_ssrc[E_MAX];   // src node, sorted by dst
__device__ float  g_et  [E_MAX];   // time value, sorted by dst

// ---------------- counting sort of edges by dst ----------------
__global__ void zero_kernel() {
    int i = blockIdx.x * blockDim.x + threadIdx.x;
    if (i < N_NODES) { g_deg[i] = 0; g_cur[i] = 0; }
}

__global__ void hist_kernel(const int* __restrict__ ei, int E) {
    int e = blockIdx.x * blockDim.x + threadIdx.x;
    if (e < E) atomicAdd(&g_deg[ei[E + e]], 1);
}

__global__ void scanA_kernel(int n) {
    __shared__ int sh[256];
    int t = threadIdx.x;
    int i = blockIdx.x * 256 + t;
    int v = (i < n) ? g_deg[i] : 0;
    sh[t] = v;
    __syncthreads();
    for (int o = 1; o < 256; o <<= 1) {
        int u = (t >= o) ? sh[t - o] : 0;
        __syncthreads();
        sh[t] += u;
        __syncthreads();
    }
    if (i < n) g_off[i] = sh[t] - v;
    if (t == 255) g_bsum[blockIdx.x] = sh[255];
}

__global__ void scanB_kernel(int nb, int n) {
    __shared__ int sh[256];
    int t = threadIdx.x;
    int v = (t < nb) ? g_bsum[t] : 0;
    sh[t] = v;
    __syncthreads();
    for (int o = 1; o < 256; o <<= 1) {
        int u = (t >= o) ? sh[t - o] : 0;
        __syncthreads();
        sh[t] += u;
        __syncthreads();
    }
    if (t < nb) g_bpre[t] = sh[t] - v;
    if (t == 255) g_off[n] = sh[255];
}

__global__ void scanC_kernel(int n) {
    int i = blockIdx.x * 256 + threadIdx.x;
    if (i < n) g_off[i] += g_bpre[blockIdx.x];
}

__global__ void scatter_kernel(const int* __restrict__ ei,
                               const float* __restrict__ ea, int E) {
    int e = blockIdx.x * blockDim.x + threadIdx.x;
    if (e >= E) return;
    int d = ei[E + e];
    int pos = g_off[d] + atomicAdd(&g_cur[d], 1);
    g_ssrc[pos] = ei[e];
    g_et[pos]   = ea[2 * e + 1];
}

// ---------------- fused node linear: q, k(fp16), v(fp16), qt, qbt ----------------
template <int D>
__global__ __launch_bounds__(128) void node_linear_kernel(
    const float* __restrict__ x_in,
    const float* __restrict__ wq, const float* __restrict__ bq,
    const float* __restrict__ wk, const float* __restrict__ bk,
    const float* __restrict__ wv, const float* __restrict__ bv,
    const float* __restrict__ wt, const float* __restrict__ bt)
{
    const float* __restrict__ x = (D == 64) ? x_in : (const float*)g_x1;
    __shared__ float xs[D * 16];        // transposed: xs[c*16 + n]
    __shared__ float qs[16 * 128];
    __shared__ float wtt[128 * 33];     // wtt[ho*33 + d] = wt[d*128 + ho]
    int col = threadIdx.x;              // 0..127
    int node0 = blockIdx.x * 16;

    for (int idx = col; idx < 16 * D; idx += 128) {
        int n = idx / D, c = idx % D;
        int node = node0 + n;
        xs[c * 16 + n] = (node < N_NODES) ? x[(size_t)node * D + c] : 0.f;
    }
    for (int idx = col; idx < 32 * 128; idx += 128) {
        int d = idx >> 7, ho = idx & 127;
        wtt[ho * 33 + d] = wt[idx];
    }
    __syncthreads();

    float aq[16], ak[16], av[16];
#pragma unroll
    for (int n = 0; n < 16; n++) { aq[n] = 0.f; ak[n] = 0.f; av[n] = 0.f; }

    const float4* xs4 = reinterpret_cast<const float4*>(xs);
    for (int c = 0; c < D; c++) {
        float wqc = wq[c * 128 + col];
        float wkc = wk[c * 128 + col];
        float wvc = wv[c * 128 + col];
        float4 a = xs4[c * 4 + 0], b = xs4[c * 4 + 1];
        float4 cc = xs4[c * 4 + 2], dd = xs4[c * 4 + 3];
        float xv[16] = {a.x, a.y, a.z, a.w, b.x, b.y, b.z, b.w,
                        cc.x, cc.y, cc.z, cc.w, dd.x, dd.y, dd.z, dd.w};
#pragma unroll
        for (int n = 0; n < 16; n++) {
            aq[n] = fmaf(xv[n], wqc, aq[n]);
            ak[n] = fmaf(xv[n], wkc, ak[n]);
            av[n] = fmaf(xv[n], wvc, av[n]);
        }
    }

    float bqc = bq[col], bkc = bk[col], bvc = bv[col];
    const float inv = 0.17677669529663688f;  // 1/sqrt(32)
#pragma unroll
    for (int n = 0; n < 16; n++) {
        int node = node0 + n;
        float qv = (aq[n] + bqc) * inv;
        qs[n * 128 + col] = qv;
        if (node < N_NODES) {
            g_q [node * 128 + col] = qv;
            g_kh[node * 128 + col] = __float2half(ak[n] + bkc);
            g_vh[node * 128 + col] = __float2half(av[n] + bvc);
        }
    }
    __syncthreads();

    int h = col >> 5, d = col & 31;
    float aqt[16];
#pragma unroll
    for (int n = 0; n < 16; n++) aqt[n] = 0.f;
    for (int c = 0; c < 32; c++) {
        float w = wtt[(h * 32 + c) * 33 + d];
#pragma unroll
        for (int n = 0; n < 16; n++)
            aqt[n] = fmaf(qs[n * 128 + h * 32 + c], w, aqt[n]);
    }
#pragma unroll
    for (int n = 0; n < 16; n++) {
        int node = node0 + n;
        if (node < N_NODES) g_qt[node * 128 + col] = aqt[n];
    }

    if (col < 4) {
        for (int n = 0; n < 16; n++) {
            int node = node0 + n;
            if (node >= N_NODES) break;
            float b = 0.f;
            for (int c = 0; c < 32; c++)
                b = fmaf(qs[n * 128 + col * 32 + c], bt[col * 32 + c], b);
            g_qbt[node * 4 + col] = b;
        }
    }
}

// ---------------- per-node softmax aggregation (warp = node, 4 heads) ----------------
// Time features inline: lane j=lane&7 covers dims 4j..4j+3 of the 32-dim encoding:
//   (sin(t*dv[2j]), cos(t*dv[2j]), sin(t*dv[2j+1]), cos(t*dv[2j+1]))
__device__ __forceinline__ float head_alpha(float4 q4, float4 qt4,
                                            float2 k01, float2 k23,
                                            float t, float dva, float dvb) {
    float a0 = t * dva, a1 = t * dvb;
    float p = q4.x * k01.x;
    p = fmaf(q4.y,  k01.y, p);
    p = fmaf(q4.z,  k23.x, p);
    p = fmaf(q4.w,  k23.y, p);
    p = fmaf(qt4.x, __sinf(a0), p);
    p = fmaf(qt4.y, __cosf(a0), p);
    p = fmaf(qt4.z, __sinf(a1), p);
    p = fmaf(qt4.w, __cosf(a1), p);
    p += __shfl_xor_sync(0xffffffffu, p, 4);
    p += __shfl_xor_sync(0xffffffffu, p, 2);
    p += __shfl_xor_sync(0xffffffffu, p, 1);
    return p;
}

template <int LAYER>
__global__ __launch_bounds__(256) void edge_agg_kernel(const float* __restrict__ wc) {
    int lane = threadIdx.x & 31;
    int node = blockIdx.x * 8 + (threadIdx.x >> 5);
    if (node >= N_NODES) return;

    int idx = g_off[node], end = g_off[node + 1];
    if (idx >= end) {
        if (LAYER == 0)
            reinterpret_cast<float4*>(g_x1 + (size_t)node * 128)[lane] =
                make_float4(0.f, 0.f, 0.f, 0.f);
        else if (lane == 0)
            g_xc[node] = 0.f;
        return;
    }

    float4 q4  = reinterpret_cast<const float4*>(g_q  + (size_t)node * 128)[lane];
    float4 qt4 = reinterpret_cast<const float4*>(g_qt + (size_t)node * 128)[lane];
    float qbt  = g_qbt[node * 4 + (lane >> 3)];

    int j = lane & 7;
    float dva = c_dv[2 * j];
    float dvb = c_dv[2 * j + 1];

    const float2* kh = reinterpret_cast<const float2*>(g_kh);
    const float2* vh = reinterpret_cast<const float2*>(g_vh);

    float s, ref;
    float4 acc;
    {   // peel first edge: reference point for exp
        int cs = g_ssrc[idx];
        float t = g_et[idx];
        float2 kraw = kh[(size_t)cs * 32 + lane];
        float2 vraw = vh[(size_t)cs * 32 + lane];
        float2 k01 = __half22float2(*reinterpret_cast<__half2*>(&kraw.x));
        float2 k23 = __half22float2(*reinterpret_cast<__half2*>(&kraw.y));
        float2 v01 = __half22float2(*reinterpret_cast<__half2*>(&vraw.x));
        float2 v23 = __half22float2(*reinterpret_cast<__half2*>(&vraw.y));
        ref = head_alpha(q4, qt4, k01, k23, t, dva, dvb) + qbt;
        s = 1.f;
        acc = make_float4(v01.x, v01.y, v23.x, v23.y);
    }
    idx++;

    int cs = 0; float t = 0.f;
    if (idx < end) { cs = g_ssrc[idx]; t = g_et[idx]; }  // prefetch
#pragma unroll 2
    for (; idx < end; idx++) {
        int   ccs = cs;
        float ct  = t;
        if (idx + 1 < end) { cs = g_ssrc[idx + 1]; t = g_et[idx + 1]; }
        float2 kraw = kh[(size_t)ccs * 32 + lane];
        float2 vraw = vh[(size_t)ccs * 32 + lane];
        float2 k01 = __half22float2(*reinterpret_cast<__half2*>(&kraw.x));
        float2 k23 = __half22float2(*reinterpret_cast<__half2*>(&kraw.y));
        float2 v01 = __half22float2(*reinterpret_cast<__half2*>(&vraw.x));
        float2 v23 = __half22float2(*reinterpret_cast<__half2*>(&vraw.y));
        float alpha = head_alpha(q4, qt4, k01, k23, ct, dva, dvb) + qbt;
        float pe = __expf(fminf(alpha - ref, 80.f));
        s += pe;
        acc.x = fmaf(pe, v01.x, acc.x);
        acc.y = fmaf(pe, v01.y, acc.y);
        acc.z = fmaf(pe, v23.x, acc.z);
        acc.w = fmaf(pe, v23.y, acc.w);
    }

    float r = 1.f / s;
    float4 o = make_float4(fmaxf(acc.x * r, 0.f), fmaxf(acc.y * r, 0.f),
                           fmaxf(acc.z * r, 0.f), fmaxf(acc.w * r, 0.f));

    if (LAYER == 0) {
        reinterpret_cast<float4*>(g_x1 + (size_t)node * 128)[lane] = o;
    } else {
        // fused classifier: xc[node] = relu(x2_row) . wc
        float4 w4 = reinterpret_cast<const float4*>(wc)[lane];
        float p = o.x * w4.x;
        p = fmaf(o.y, w4.y, p);
        p = fmaf(o.z, w4.z, p);
        p = fmaf(o.w, w4.w, p);
#pragma unroll
        for (int off = 16; off; off >>= 1)
            p += __shfl_xor_sync(0xffffffffu, p, off);
        if (lane == 0) g_xc[node] = p;
    }
}

// ---------------- final: out[e] = xc[src] + xc[dst] + bc ----------------
__global__ void final_kernel(const int* __restrict__ ei, const float* __restrict__ bc,
                             float* __restrict__ out, int E) {
    int e = blockIdx.x * blockDim.x + threadIdx.x;
    if (e >= E) return;
    out[e] = g_xc[ei[e]] + g_xc[ei[E + e]] + bc[0];
}

// ---------------- launch ----------------
extern "C" void kernel_launch(void* const* d_in, const int* in_sizes, int n_in,
                              void* d_out, int out_size) {
    const int*   ei  = (const int*)  d_in[0];
    const float* ea  = (const float*)d_in[1];
    const float* emb = (const float*)d_in[3];
    const float *wq1 = (const float*)d_in[4],  *bq1 = (const float*)d_in[5];
    const float *wk1 = (const float*)d_in[6],  *bk1 = (const float*)d_in[7];
    const float *wv1 = (const float*)d_in[8],  *bv1 = (const float*)d_in[9];
    const float *wt1 = (const float*)d_in[10], *bt1 = (const float*)d_in[11];
    const float *wq2 = (const float*)d_in[12], *bq2 = (const float*)d_in[13];
    const float *wk2 = (const float*)d_in[14], *bk2 = (const float*)d_in[15];
    const float *wv2 = (const float*)d_in[16], *bv2 = (const float*)d_in[17];
    const float *wt2 = (const float*)d_in[18], *bt2 = (const float*)d_in[19];
    const float *wc  = (const float*)d_in[20], *bc  = (const float*)d_in[21];
    float* out = (float*)d_out;

    int E = in_sizes[0] / 2;

    zero_kernel<<<(N_NODES + 255) / 256, 256>>>();
    hist_kernel<<<(E + 255) / 256, 256>>>(ei, E);
    scanA_kernel<<<SCAN_BLOCKS, 256>>>(N_NODES);
    scanB_kernel<<<1, 256>>>(SCAN_BLOCKS, N_NODES);
    scanC_kernel<<<SCAN_BLOCKS, 256>>>(N_NODES);
    scatter_kernel<<<(E + 255) / 256, 256>>>(ei, ea, E);

    // layer 1 (x = emb[:N], D=64)
    node_linear_kernel<64><<<(N_NODES + 15) / 16, 128>>>(emb, wq1, bq1, wk1, bk1, wv1, bv1, wt1, bt1);
    edge_agg_kernel<0><<<(N_NODES + 7) / 8, 256>>>(wc);

    // layer 2 (x = g_x1, D=128), classifier fused into aggregation
    node_linear_kernel<128><<<(N_NODES + 15) / 16, 128>>>(emb, wq2, bq2, wk2, bk2, wv2, bv2, wt2, bt2);
    edge_agg_kernel<1><<<(N_NODES + 7) / 8, 256>>>(wc);

    final_kernel<<<(E + 255) / 256, 256>>>(ei, bc, out, E);
}

// round 6
// speedup vs baseline: 2.3266x; 1.3447x over previous
#include <cuda_runtime.h>
#include <cuda_fp16.h>
#include <mma.h>
#include <math.h>
using namespace nvcuda;

#define N_NODES 50000
#define N_PAD   50016     // multiple of 32
#define E_MAX   800000
#define SCAN_BLOCKS 196   // 196*256 = 50176 >= 50000

// div_term[i] = 10^(-i/4) = exp(-i*ln(10000)/16), i = 0..15 (exact table)
__constant__ float c_dv[16] = {
    1.0f, 0.5623413251903491f, 0.31622776601683794f, 0.17782794100389228f,
    0.1f, 0.05623413251903491f, 0.031622776601683794f, 0.017782794100389228f,
    0.01f, 0.005623413251903491f, 0.0031622776601683794f, 0.0017782794100389228f,
    0.001f, 0.0005623413251903491f, 0.00031622776601683794f, 0.00017782794100389228f};

// ---------------- static device scratch (zero-initialized, incl. pad rows) ----------------
__device__ float  g_q  [N_PAD * 128];
__device__ __half g_kh [N_PAD * 128];
__device__ __half g_vh [N_PAD * 128];
__device__ float  g_qt [N_PAD * 128];
__device__ float  g_qbt[N_PAD * 4];
__device__ __half g_xh [N_PAD * 64];    // emb -> half
__device__ __half g_x1h[N_PAD * 128];   // layer-1 output (half), pad rows stay 0
__device__ float  g_xc [N_NODES];
__device__ __half g_w1 [3 * 64 * 128];  // wq1|wk1|wv1 as half
__device__ __half g_wt1[32 * 128];
__device__ __half g_w2 [3 * 128 * 128];
__device__ __half g_wt2[32 * 128];
__device__ int    g_deg[N_NODES];
__device__ int    g_cur[N_NODES];
__device__ int    g_off[N_NODES + 1];
__device__ int    g_bsum[SCAN_BLOCKS];
__device__ int    g_bpre[SCAN_BLOCKS];
__device__ int    g_ssrc[E_MAX];
__device__ float  g_et  [E_MAX];

// ---------------- fp32 -> fp16 conversions (device globals referenced in device code only) ----------------
__global__ void conv_emb_kernel(const float* __restrict__ emb) {
    int i = blockIdx.x * 256 + threadIdx.x;
    if (i < N_NODES * 64) g_xh[i] = __float2half(emb[i]);
}

template <int L>
__global__ void convw_kernel(const float* __restrict__ wq, const float* __restrict__ wk,
                             const float* __restrict__ wv, const float* __restrict__ wt) {
    constexpr int D = (L == 0) ? 64 : 128;
    __half* __restrict__ wdst  = (L == 0) ? g_w1  : g_w2;
    __half* __restrict__ wtdst = (L == 0) ? g_wt1 : g_wt2;
    int i = blockIdx.x * 256 + threadIdx.x;
    const int per = D * 128;
    if (i < 3 * per) {
        const float* s = (i < per) ? wq : ((i < 2 * per) ? wk : wv);
        wdst[i] = __float2half(s[i % per]);
    }
    if (i < 32 * 128) wtdst[i] = __float2half(wt[i]);
}

// ---------------- counting sort of edges by dst ----------------
__global__ void zero_kernel() {
    int i = blockIdx.x * blockDim.x + threadIdx.x;
    if (i < N_NODES) { g_deg[i] = 0; g_cur[i] = 0; }
}

__global__ void hist_kernel(const int* __restrict__ ei, int E) {
    int e = blockIdx.x * blockDim.x + threadIdx.x;
    if (e < E) atomicAdd(&g_deg[ei[E + e]], 1);
}

__global__ void scanA_kernel(int n) {
    __shared__ int sh[256];
    int t = threadIdx.x;
    int i = blockIdx.x * 256 + t;
    int v = (i < n) ? g_deg[i] : 0;
    sh[t] = v;
    __syncthreads();
    for (int o = 1; o < 256; o <<= 1) {
        int u = (t >= o) ? sh[t - o] : 0;
        __syncthreads();
        sh[t] += u;
        __syncthreads();
    }
    if (i < n) g_off[i] = sh[t] - v;
    if (t == 255) g_bsum[blockIdx.x] = sh[255];
}

__global__ void scanB_kernel(int nb, int n) {
    __shared__ int sh[256];
    int t = threadIdx.x;
    int v = (t < nb) ? g_bsum[t] : 0;
    sh[t] = v;
    __syncthreads();
    for (int o = 1; o < 256; o <<= 1) {
        int u = (t >= o) ? sh[t - o] : 0;
        __syncthreads();
        sh[t] += u;
        __syncthreads();
    }
    if (t < nb) g_bpre[t] = sh[t] - v;
    if (t == 255) g_off[n] = sh[255];
}

__global__ void scanC_kernel(int n) {
    int i = blockIdx.x * 256 + threadIdx.x;
    if (i < n) g_off[i] += g_bpre[blockIdx.x];
}

__global__ void scatter_kernel(const int* __restrict__ ei,
                               const float* __restrict__ ea, int E) {
    int e = blockIdx.x * blockDim.x + threadIdx.x;
    if (e >= E) return;
    int d = ei[E + e];
    int pos = g_off[d] + atomicAdd(&g_cur[d], 1);
    g_ssrc[pos] = ei[e];
    g_et[pos]   = ea[2 * e + 1];
}

// ---------------- tensor-core node linear: q, k(fp16), v(fp16), qt, qbt ----------------
// Block = 256 threads (8 warps), 32 nodes. Warp w computes cols [w*16, w*16+16)
// of each of q,k,v (fp32 accum), then per-head qt GEMM, then scalar qbt.
template <int L>
__global__ __launch_bounds__(256) void node_linear_wmma(
    const float* __restrict__ bq, const float* __restrict__ bk,
    const float* __restrict__ bv, const float* __restrict__ bt)
{
    constexpr int D = (L == 0) ? 64 : 128;
    const __half* __restrict__ xh  = (L == 0) ? g_xh  : g_x1h;
    const __half* __restrict__ wh  = (L == 0) ? g_w1  : g_w2;
    const __half* __restrict__ wth = (L == 0) ? g_wt1 : g_wt2;

    __shared__ float  stage[32 * 128];   // 16 KB: one matrix at a time
    __shared__ __half qsh[32 * 128];     // 8 KB: scaled q' (half)
    const int w = threadIdx.x >> 5;
    const int node0 = blockIdx.x * 32;

    wmma::fragment<wmma::accumulator, 16, 16, 16, float> acc[3][2];
#pragma unroll
    for (int m = 0; m < 3; m++)
#pragma unroll
        for (int r = 0; r < 2; r++) wmma::fill_fragment(acc[m][r], 0.f);

#pragma unroll
    for (int k0 = 0; k0 < D; k0 += 16) {
        wmma::fragment<wmma::matrix_a, 16, 16, 16, __half, wmma::row_major> a0, a1;
        wmma::load_matrix_sync(a0, xh + (size_t)node0 * D + k0, D);
        wmma::load_matrix_sync(a1, xh + (size_t)(node0 + 16) * D + k0, D);
#pragma unroll
        for (int m = 0; m < 3; m++) {
            wmma::fragment<wmma::matrix_b, 16, 16, 16, __half, wmma::row_major> b;
            wmma::load_matrix_sync(b, wh + m * (D * 128) + k0 * 128 + w * 16, 128);
            wmma::mma_sync(acc[m][0], a0, b, acc[m][0]);
            wmma::mma_sync(acc[m][1], a1, b, acc[m][1]);
        }
    }

    const float inv = 0.17677669529663688f;  // 1/sqrt(32)
#pragma unroll
    for (int m = 0; m < 3; m++) {
        wmma::store_matrix_sync(stage + w * 16, acc[m][0], 128, wmma::mem_row_major);
        wmma::store_matrix_sync(stage + 16 * 128 + w * 16, acc[m][1], 128, wmma::mem_row_major);
        __syncthreads();
        for (int i = threadIdx.x; i < 32 * 128; i += 256) {
            int c = i & 127;
            int node = node0 + (i >> 7);
            float val = stage[i];
            if (m == 0) {
                float qv = (val + bq[c]) * inv;
                qsh[i] = __float2half(qv);
                g_q[(size_t)node * 128 + c] = qv;
            } else if (m == 1) {
                g_kh[(size_t)node * 128 + c] = __float2half(val + bk[c]);
            } else {
                g_vh[(size_t)node * 128 + c] = __float2half(val + bv[c]);
            }
        }
        __syncthreads();
    }

    // qt GEMM: per-head 32x32; warp w -> head h = w>>1, col offset d0 = (w&1)*16
    {
        int h = w >> 1, d0 = (w & 1) * 16;
        wmma::fragment<wmma::accumulator, 16, 16, 16, float> q0, q1;
        wmma::fill_fragment(q0, 0.f);
        wmma::fill_fragment(q1, 0.f);
#pragma unroll
        for (int k0 = 0; k0 < 32; k0 += 16) {
            wmma::fragment<wmma::matrix_a, 16, 16, 16, __half, wmma::row_major> a0, a1;
            wmma::fragment<wmma::matrix_b, 16, 16, 16, __half, wmma::col_major> b;
            wmma::load_matrix_sync(a0, qsh + h * 32 + k0, 128);
            wmma::load_matrix_sync(a1, qsh + 16 * 128 + h * 32 + k0, 128);
            // wt[d, h*32+c]: B[k=c, n=d] at wth[(d0+d)*128 + h*32 + k0 + c] -> col_major ldm=128
            wmma::load_matrix_sync(b, wth + h * 32 + k0 + d0 * 128, 128);
            wmma::mma_sync(q0, a0, b, q0);
            wmma::mma_sync(q1, a1, b, q1);
        }
        wmma::store_matrix_sync(g_qt + (size_t)node0 * 128 + h * 32 + d0, q0, 128, wmma::mem_row_major);
        wmma::store_matrix_sync(g_qt + (size_t)(node0 + 16) * 128 + h * 32 + d0, q1, 128, wmma::mem_row_major);
    }

    // qbt: node n, head hh -> dot(q'[n, hh*32:+32], bt[hh*32:+32])
    if (threadIdx.x < 128) {
        int n = threadIdx.x >> 2, hh = threadIdx.x & 3;
        float b = 0.f;
#pragma unroll
        for (int c = 0; c < 32; c++)
            b = fmaf(__half2float(qsh[n * 128 + hh * 32 + c]), bt[hh * 32 + c], b);
        g_qbt[(size_t)(node0 + n) * 4 + hh] = b;
    }
}

// ---------------- per-node softmax aggregation (warp = node, 4 heads) ----------------
__device__ __forceinline__ float head_alpha(float4 q4, float4 qt4,
                                            float2 k01, float2 k23,
                                            float t, float dva, float dvb) {
    float a0 = t * dva, a1 = t * dvb;
    float p = q4.x * k01.x;
    p = fmaf(q4.y,  k01.y, p);
    p = fmaf(q4.z,  k23.x, p);
    p = fmaf(q4.w,  k23.y, p);
    p = fmaf(qt4.x, __sinf(a0), p);
    p = fmaf(qt4.y, __cosf(a0), p);
    p = fmaf(qt4.z, __sinf(a1), p);
    p = fmaf(qt4.w, __cosf(a1), p);
    p += __shfl_xor_sync(0xffffffffu, p, 4);
    p += __shfl_xor_sync(0xffffffffu, p, 2);
    p += __shfl_xor_sync(0xffffffffu, p, 1);
    return p;
}

template <int LAYER>
__global__ __launch_bounds__(256) void edge_agg_kernel(const float* __restrict__ wc) {
    int lane = threadIdx.x & 31;
    int node = blockIdx.x * 8 + (threadIdx.x >> 5);
    if (node >= N_NODES) return;

    int idx = g_off[node], end = g_off[node + 1];
    if (idx >= end) {
        if (LAYER == 0) {
            reinterpret_cast<uint2*>(g_x1h + (size_t)node * 128)[lane] = make_uint2(0u, 0u);
        } else if (lane == 0) {
            g_xc[node] = 0.f;
        }
        return;
    }

    float4 q4  = reinterpret_cast<const float4*>(g_q  + (size_t)node * 128)[lane];
    float4 qt4 = reinterpret_cast<const float4*>(g_qt + (size_t)node * 128)[lane];
    float qbt  = g_qbt[(size_t)node * 4 + (lane >> 3)];

    int j = lane & 7;
    float dva = c_dv[2 * j];
    float dvb = c_dv[2 * j + 1];

    const float2* kh = reinterpret_cast<const float2*>(g_kh);
    const float2* vh = reinterpret_cast<const float2*>(g_vh);

    float s, ref;
    float4 acc;
    {   // peel first edge: reference point for exp
        int cs = g_ssrc[idx];
        float t = g_et[idx];
        float2 kraw = kh[(size_t)cs * 32 + lane];
        float2 vraw = vh[(size_t)cs * 32 + lane];
        float2 k01 = __half22float2(*reinterpret_cast<__half2*>(&kraw.x));
        float2 k23 = __half22float2(*reinterpret_cast<__half2*>(&kraw.y));
        float2 v01 = __half22float2(*reinterpret_cast<__half2*>(&vraw.x));
        float2 v23 = __half22float2(*reinterpret_cast<__half2*>(&vraw.y));
        ref = head_alpha(q4, qt4, k01, k23, t, dva, dvb) + qbt;
        s = 1.f;
        acc = make_float4(v01.x, v01.y, v23.x, v23.y);
    }
    idx++;

    int cs = 0; float t = 0.f;
    if (idx < end) { cs = g_ssrc[idx]; t = g_et[idx]; }  // prefetch
#pragma unroll 2
    for (; idx < end; idx++) {
        int   ccs = cs;
        float ct  = t;
        if (idx + 1 < end) { cs = g_ssrc[idx + 1]; t = g_et[idx + 1]; }
        float2 kraw = kh[(size_t)ccs * 32 + lane];
        float2 vraw = vh[(size_t)ccs * 32 + lane];
        float2 k01 = __half22float2(*reinterpret_cast<__half2*>(&kraw.x));
        float2 k23 = __half22float2(*reinterpret_cast<__half2*>(&kraw.y));
        float2 v01 = __half22float2(*reinterpret_cast<__half2*>(&vraw.x));
        float2 v23 = __half22float2(*reinterpret_cast<__half2*>(&vraw.y));
        float alpha = head_alpha(q4, qt4, k01, k23, ct, dva, dvb) + qbt;
        float pe = __expf(fminf(alpha - ref, 80.f));
        s += pe;
        acc.x = fmaf(pe, v01.x, acc.x);
        acc.y = fmaf(pe, v01.y, acc.y);
        acc.z = fmaf(pe, v23.x, acc.z);
        acc.w = fmaf(pe, v23.y, acc.w);
    }

    float r = 1.f / s;
    float4 o = make_float4(fmaxf(acc.x * r, 0.f), fmaxf(acc.y * r, 0.f),
                           fmaxf(acc.z * r, 0.f), fmaxf(acc.w * r, 0.f));

    if (LAYER == 0) {
        __half2 h01 = __floats2half2_rn(o.x, o.y);
        __half2 h23 = __floats2half2_rn(o.z, o.w);
        uint2 u;
        u.x = *reinterpret_cast<unsigned*>(&h01);
        u.y = *reinterpret_cast<unsigned*>(&h23);
        reinterpret_cast<uint2*>(g_x1h + (size_t)node * 128)[lane] = u;
    } else {
        // fused classifier: xc[node] = relu(x2_row) . wc
        float4 w4 = reinterpret_cast<const float4*>(wc)[lane];
        float p = o.x * w4.x;
        p = fmaf(o.y, w4.y, p);
        p = fmaf(o.z, w4.z, p);
        p = fmaf(o.w, w4.w, p);
#pragma unroll
        for (int off = 16; off; off >>= 1)
            p += __shfl_xor_sync(0xffffffffu, p, off);
        if (lane == 0) g_xc[node] = p;
    }
}

// ---------------- final: out[e] = xc[src] + xc[dst] + bc ----------------
__global__ void final_kernel(const int* __restrict__ ei, const float* __restrict__ bc,
                             float* __restrict__ out, int E) {
    int e = blockIdx.x * blockDim.x + threadIdx.x;
    if (e >= E) return;
    out[e] = g_xc[ei[e]] + g_xc[ei[E + e]] + bc[0];
}

// ---------------- launch ----------------
extern "C" void kernel_launch(void* const* d_in, const int* in_sizes, int n_in,
                              void* d_out, int out_size) {
    const int*   ei  = (const int*)  d_in[0];
    const float* ea  = (const float*)d_in[1];
    const float* emb = (const float*)d_in[3];
    const float *wq1 = (const float*)d_in[4],  *bq1 = (const float*)d_in[5];
    const float *wk1 = (const float*)d_in[6],  *bk1 = (const float*)d_in[7];
    const float *wv1 = (const float*)d_in[8],  *bv1 = (const float*)d_in[9];
    const float *wt1 = (const float*)d_in[10], *bt1 = (const float*)d_in[11];
    const float *wq2 = (const float*)d_in[12], *bq2 = (const float*)d_in[13];
    const float *wk2 = (const float*)d_in[14], *bk2 = (const float*)d_in[15];
    const float *wv2 = (const float*)d_in[16], *bv2 = (const float*)d_in[17];
    const float *wt2 = (const float*)d_in[18], *bt2 = (const float*)d_in[19];
    const float *wc  = (const float*)d_in[20], *bc  = (const float*)d_in[21];
    float* out = (float*)d_out;

    int E = in_sizes[0] / 2;

    // conversions (independent of sort chain)
    conv_emb_kernel<<<(N_NODES * 64 + 255) / 256, 256>>>(emb);
    convw_kernel<0><<<(3 * 64 * 128 + 255) / 256, 256>>>(wq1, wk1, wv1, wt1);
    convw_kernel<1><<<(3 * 128 * 128 + 255) / 256, 256>>>(wq2, wk2, wv2, wt2);

    // counting sort by dst
    zero_kernel<<<(N_NODES + 255) / 256, 256>>>();
    hist_kernel<<<(E + 255) / 256, 256>>>(ei, E);
    scanA_kernel<<<SCAN_BLOCKS, 256>>>(N_NODES);
    scanB_kernel<<<1, 256>>>(SCAN_BLOCKS, N_NODES);
    scanC_kernel<<<SCAN_BLOCKS, 256>>>(N_NODES);
    scatter_kernel<<<(E + 255) / 256, 256>>>(ei, ea, E);

    // layer 1 (x = emb half, D=64)
    node_linear_wmma<0><<<N_PAD / 32, 256>>>(bq1, bk1, bv1, bt1);
    edge_agg_kernel<0><<<(N_NODES + 7) / 8, 256>>>(wc);

    // layer 2 (x = g_x1h, D=128), classifier fused
    node_linear_wmma<1><<<N_PAD / 32, 256>>>(bq2, bk2, bv2, bt2);
    edge_agg_kernel<1><<<(N_NODES + 7) / 8, 256>>>(wc);

    final_kernel<<<(E + 255) / 256, 256>>>(ei, bc, out, E);
}